// round 5
// baseline (speedup 1.0000x reference)
#include <cuda_runtime.h>
#include <cuda_fp16.h>
#include <cstdint>

// Shapes: B=64, T=2048, A=D=U=512
// inputs(64,512) h(64,512) c(64,512) annotations(64,2048,512)
// kernel(1024,2048) recurrent_kernel(512,2048) bias(3072)
// kernel_u(512,512) kernel_w(512,512) kernel_v(512)
// out: h_new (64,512) fp32

// ---------------- device scratch (no allocations allowed) ----------------
__device__ __half g_ku[512 * 512];          // kernel_u in fp16
__device__ float g_s[64 * 512];             // h@kernel_w + bias_u
__device__ float g_et[64 * 2048];           // et, then at (in place)
__device__ float g_ctx[64 * 512];           // context
__device__ float g_z[64 * 2048];            // gate pre-activations

// ---------------- helpers ----------------
// Accurate tanh: tanh(x) = 1 - 2/(exp(2x)+1), via ex2.approx + rcp.approx.
__device__ __forceinline__ float tanhp(float x) {
    float e, r;
    asm("ex2.approx.f32 %0, %1;" : "=f"(e) : "f"(x * 2.88539008177793f)); // 2*log2(e)
    asm("rcp.approx.f32 %0, %1;" : "=f"(r) : "f"(e + 1.0f));
    return 1.0f - 2.0f * r;
}

__device__ __forceinline__ void mma16816(float* c,
                                         uint32_t a0, uint32_t a1, uint32_t a2, uint32_t a3,
                                         uint32_t b0, uint32_t b1) {
    asm volatile(
        "mma.sync.aligned.m16n8k16.row.col.f32.f16.f16.f32 "
        "{%0,%1,%2,%3},{%4,%5,%6,%7},{%8,%9},{%0,%1,%2,%3};"
        : "+f"(c[0]), "+f"(c[1]), "+f"(c[2]), "+f"(c[3])
        : "r"(a0), "r"(a1), "r"(a2), "r"(a3), "r"(b0), "r"(b1));
}

// ---------------- kernel P: kernel_u fp32 -> fp16 ----------------
__global__ void k_prep(const float* __restrict__ ku) {
    int i = blockIdx.x * blockDim.x + threadIdx.x;
    int stride = gridDim.x * blockDim.x;
    for (; i < 512 * 512; i += stride)
        g_ku[i] = __float2half(ku[i]);
}

// ---------------- kernel A: s = h @ kernel_w + bias_u ----------------
__global__ void k_s(const float* __restrict__ h, const float* __restrict__ kw,
                    const float* __restrict__ bias) {
    __shared__ float hs[512];
    int b = blockIdx.x, u = threadIdx.x;
    hs[u] = h[b * 512 + u];
    __syncthreads();
    float acc = bias[2048 + u];   // bias_u = bias[4U:5U]
#pragma unroll 8
    for (int k = 0; k < 512; k++)
        acc += hs[k] * kw[k * 512 + u];
    g_s[b * 512 + u] = acc;
}

// ---------------- kernel B: attention scores et ----------------
// Per block: b = blockIdx.y, t-tile = 128 rows at t0 = blockIdx.x*128.
// et[b,t] = sum_u tanh(ann[b,t,:]@ku[:,u] + s[b,u]) * kv[u]
static constexpr int SA = 520;   // As row stride (fp16) — conflict-free frag loads
static constexpr int SB = 136;   // Bs row stride (fp16)
static constexpr int SMEM_ATT = 128 * SA * 2 + 64 * SB * 2 + 2 * 512 * 4; // 154624

__global__ __launch_bounds__(256) void k_att(const float* __restrict__ ann,
                                             const float* __restrict__ kv) {
    extern __shared__ char sm[];
    __half* As = (__half*)sm;                               // [128][SA]
    __half* Bs = (__half*)(sm + 128 * SA * 2);              // [64][SB]
    float* s_s = (float*)(sm + 128 * SA * 2 + 64 * SB * 2); // [512]
    float* kv_s = s_s + 512;                                // [512]

    int b = blockIdx.y;
    int t0 = blockIdx.x * 128;
    int tid = threadIdx.x;

    for (int i = tid; i < 512; i += 256) {
        s_s[i] = g_s[b * 512 + i];
        kv_s[i] = kv[i];
    }

    // Load A tile: ann[b, t0:t0+128, 0:512] fp32 -> fp16 smem
    const float* arow = ann + ((size_t)b * 2048 + t0) * 512;
    for (int i = tid; i < 128 * 128; i += 256) {   // float4 granules
        int r = i >> 7;
        int c4 = (i & 127) * 4;
        float4 v = *(const float4*)(arow + (size_t)r * 512 + c4);
        __half2 p0, p1;
        p0.x = __float2half(v.x); p0.y = __float2half(v.y);
        p1.x = __float2half(v.z); p1.y = __float2half(v.w);
        *(__half2*)(As + r * SA + c4) = p0;
        *(__half2*)(As + r * SA + c4 + 2) = p1;
    }

    int w = tid >> 5;
    int lane = tid & 31;
    int g = lane >> 2;    // group id (row within 16-row stripe)
    int tg = lane & 3;    // thread-in-group

    float p1acc = 0.f, p2acc = 0.f;

    for (int uc = 0; uc < 8; uc++) {
        float acc[8][4];
#pragma unroll
        for (int n0 = 0; n0 < 8; n0++)
#pragma unroll
            for (int q = 0; q < 4; q++) acc[n0][q] = 0.f;

        for (int kc = 0; kc < 4; kc++) {
            __syncthreads();   // protect Bs (and A tile on first pass)
            // Load Bs chunk transposed: g_ku[kc*128+kk][uc*64+uu] -> Bs[uu][kk]
            for (int i = tid; i < 8192; i += 256) {
                int kk = i >> 6, uu = i & 63;
                Bs[uu * SB + kk] = g_ku[(kc * 128 + kk) * 512 + uc * 64 + uu];
            }
            __syncthreads();

#pragma unroll
            for (int ks = 0; ks < 8; ks++) {
                int k0 = ks * 16;
                // FIX: A must advance through the kc K-chunk (kc*128 offset was missing)
                const __half* ab = As + (w * 16 + g) * SA + kc * 128 + k0 + tg * 2;
                uint32_t a0 = *(const uint32_t*)ab;
                uint32_t a1 = *(const uint32_t*)(ab + 8 * SA);
                uint32_t a2 = *(const uint32_t*)(ab + 8);
                uint32_t a3 = *(const uint32_t*)(ab + 8 * SA + 8);
#pragma unroll
                for (int n0 = 0; n0 < 8; n0++) {
                    const __half* bb = Bs + (n0 * 8 + g) * SB + k0 + tg * 2;
                    uint32_t b0 = *(const uint32_t*)bb;
                    uint32_t b1 = *(const uint32_t*)(bb + 8);
                    mma16816(acc[n0], a0, a1, a2, a3, b0, b1);
                }
            }
        }

        // Epilogue for this u-chunk: tanh(uh + s) * kv, fold into row partials
#pragma unroll
        for (int n0 = 0; n0 < 8; n0++) {
            int ub = uc * 64 + n0 * 8 + tg * 2;
            float s0 = s_s[ub], s1 = s_s[ub + 1];
            float v0 = kv_s[ub], v1 = kv_s[ub + 1];
            p1acc += tanhp(acc[n0][0] + s0) * v0 + tanhp(acc[n0][1] + s1) * v1;
            p2acc += tanhp(acc[n0][2] + s0) * v0 + tanhp(acc[n0][3] + s1) * v1;
        }
    }

    // Reduce across the 4 lanes sharing a row
    p1acc += __shfl_xor_sync(0xffffffffu, p1acc, 1);
    p1acc += __shfl_xor_sync(0xffffffffu, p1acc, 2);
    p2acc += __shfl_xor_sync(0xffffffffu, p2acc, 1);
    p2acc += __shfl_xor_sync(0xffffffffu, p2acc, 2);
    if (tg == 0) {
        g_et[b * 2048 + t0 + w * 16 + g] = p1acc;
        g_et[b * 2048 + t0 + w * 16 + g + 8] = p2acc;
    }
}

// ---------------- kernel C: softmax over t (in place), zero ctx ----------------
__global__ void k_softmax() {
    __shared__ float red[512];
    int b = blockIdx.x, tid = threadIdx.x;
    float v[4];
    float mx = -1e30f;
#pragma unroll
    for (int j = 0; j < 4; j++) {
        v[j] = g_et[b * 2048 + j * 512 + tid];
        mx = fmaxf(mx, v[j]);
    }
    red[tid] = mx;
    __syncthreads();
    for (int s = 256; s > 0; s >>= 1) {
        if (tid < s) red[tid] = fmaxf(red[tid], red[tid + s]);
        __syncthreads();
    }
    mx = red[0];
    __syncthreads();
    float sum = 0.f;
#pragma unroll
    for (int j = 0; j < 4; j++) {
        v[j] = expf(v[j] - mx);
        sum += v[j];
    }
    red[tid] = sum;
    __syncthreads();
    for (int s = 256; s > 0; s >>= 1) {
        if (tid < s) red[tid] += red[tid + s];
        __syncthreads();
    }
    float inv = 1.f / red[0];
#pragma unroll
    for (int j = 0; j < 4; j++)
        g_et[b * 2048 + j * 512 + tid] = v[j] * inv;
    g_ctx[b * 512 + tid] = 0.f;
}

// ---------------- kernel D: context = at . annotations ----------------
__global__ __launch_bounds__(256) void k_ctx(const float* __restrict__ ann) {
    __shared__ float at_s[512];
    int ac = blockIdx.x, tc = blockIdx.y, b = blockIdx.z;
    int tid = threadIdx.x;
    int tbase = tc * 512, a0 = ac * 256;
    at_s[tid] = g_et[b * 2048 + tbase + tid];
    at_s[tid + 256] = g_et[b * 2048 + tbase + tid + 256];
    __syncthreads();
    const float* base = ann + ((size_t)b * 2048 + tbase) * 512 + a0 + tid;
    float acc = 0.f;
#pragma unroll 4
    for (int t = 0; t < 512; t++)
        acc += at_s[t] * base[(size_t)t * 512];
    atomicAdd(&g_ctx[b * 512 + a0 + tid], acc);
}

// ---------------- kernel E1: z = [inputs,ctx,h] @ [kernel;rk] + bias ----------------
__global__ __launch_bounds__(256) void k_z(const float* __restrict__ inputs,
                                           const float* __restrict__ h,
                                           const float* __restrict__ kern,
                                           const float* __restrict__ rk,
                                           const float* __restrict__ bias) {
    __shared__ float xs[64][33];
    __shared__ float ws[32][33];
    int j0 = blockIdx.x * 32;
    int tid = threadIdx.x;
    int tj = tid & 15, tb = tid >> 4;
    float acc[4][2] = {};
    for (int kc = 0; kc < 48; kc++) {
        int k0 = kc * 32;
        for (int i = tid; i < 2048; i += 256) {
            int bb = i >> 5, k = i & 31;
            int kk = k0 + k;
            float v;
            if (kk < 512)        v = inputs[bb * 512 + kk];
            else if (kk < 1024)  v = g_ctx[bb * 512 + kk - 512];
            else                 v = h[bb * 512 + kk - 1024];
            xs[bb][k] = v;
        }
        for (int i = tid; i < 1024; i += 256) {
            int k = i >> 5, j = i & 31;
            int kk = k0 + k;
            float v = (kk < 1024) ? kern[(size_t)kk * 2048 + j0 + j]
                                  : rk[(size_t)(kk - 1024) * 2048 + j0 + j];
            ws[k][j] = v;
        }
        __syncthreads();
#pragma unroll 8
        for (int k = 0; k < 32; k++) {
            float w0 = ws[k][tj * 2], w1 = ws[k][tj * 2 + 1];
#pragma unroll
            for (int bb = 0; bb < 4; bb++) {
                float x = xs[tb * 4 + bb][k];
                acc[bb][0] += x * w0;
                acc[bb][1] += x * w1;
            }
        }
        __syncthreads();
    }
#pragma unroll
    for (int bb = 0; bb < 4; bb++) {
        int bi = tb * 4 + bb;
        int j = j0 + tj * 2;
        g_z[bi * 2048 + j]     = acc[bb][0] + bias[j];
        g_z[bi * 2048 + j + 1] = acc[bb][1] + bias[j + 1];
    }
}

// ---------------- kernel E2: gates + h_new ----------------
__global__ void k_gate(const float* __restrict__ c, float* __restrict__ out) {
    int b = blockIdx.x, u = threadIdx.x;
    float zi = g_z[b * 2048 + u];
    float zf = g_z[b * 2048 + 512 + u];
    float zg = g_z[b * 2048 + 1024 + u];
    float zo = g_z[b * 2048 + 1536 + u];
    float ig = fminf(fmaxf(0.2f * zi + 0.5f, 0.f), 1.f);
    float fg = fminf(fmaxf(0.2f * zf + 0.5f, 0.f), 1.f);
    float og = fminf(fmaxf(0.2f * zo + 0.5f, 0.f), 1.f);
    float cn = fg * c[b * 512 + u] + ig * tanhf(zg);
    out[b * 512 + u] = og * tanhf(cn);
}

// ---------------- launch ----------------
extern "C" void kernel_launch(void* const* d_in, const int* in_sizes, int n_in,
                              void* d_out, int out_size) {
    const float* inputs = (const float*)d_in[0];
    const float* h      = (const float*)d_in[1];
    const float* c      = (const float*)d_in[2];
    const float* ann    = (const float*)d_in[3];
    const float* kern   = (const float*)d_in[4];
    const float* rk     = (const float*)d_in[5];
    const float* bias   = (const float*)d_in[6];
    const float* ku     = (const float*)d_in[7];
    const float* kw     = (const float*)d_in[8];
    const float* kv     = (const float*)d_in[9];
    float* out = (float*)d_out;

    cudaFuncSetAttribute(k_att, cudaFuncAttributeMaxDynamicSharedMemorySize, SMEM_ATT);

    k_prep<<<512, 256>>>(ku);
    k_s<<<64, 512>>>(h, kw, bias);
    dim3 gb(16, 64);
    k_att<<<gb, 256, SMEM_ATT>>>(ann, kv);
    k_softmax<<<64, 512>>>();
    dim3 gd(2, 4, 64);
    k_ctx<<<gd, 256>>>(ann);
    k_z<<<64, 256>>>(inputs, h, kern, rk, bias);
    k_gate<<<64, 512>>>(c, out);
}

// round 7
// speedup vs baseline: 1.4891x; 1.4891x over previous
#include <cuda_runtime.h>
#include <cuda_fp16.h>
#include <cstdint>

// Shapes: B=64, T=2048, A=D=U=512
// NOTE (R6 lesson): harness PTX target is sm_103 (no 'a') -> tcgen05 unavailable.
// This is the optimized legacy-HMMA path.

// ---------------- device scratch ----------------
__device__ __half g_kuT[512 * 512];         // kernel_u transposed [u][k], fp16
__device__ float g_s[64 * 512];             // h@kernel_w + bias_u
__device__ float g_et[64 * 2048];           // et, then at (in place)
__device__ float g_ctx[64 * 512];           // context
__device__ float g_z[64 * 2048];            // gate pre-activations

// ---------------- helpers ----------------
__device__ __forceinline__ uint32_t smem_u32(const void* p) {
    uint32_t a;
    asm("{ .reg .u64 t; cvta.to.shared.u64 t, %1; cvt.u32.u64 %0, t; }" : "=r"(a) : "l"(p));
    return a;
}

// Accurate tanh: 1 - 2/(exp(2x)+1) via ex2+rcp (~2^-22 rel err)
__device__ __forceinline__ float tanhp(float x) {
    float e, r;
    asm("ex2.approx.f32 %0, %1;" : "=f"(e) : "f"(x * 2.88539008177793f));
    asm("rcp.approx.f32 %0, %1;" : "=f"(r) : "f"(e + 1.0f));
    return 1.0f - 2.0f * r;
}

__device__ __forceinline__ void mma16816(float* c,
                                         uint32_t a0, uint32_t a1, uint32_t a2, uint32_t a3,
                                         uint32_t b0, uint32_t b1) {
    asm volatile(
        "mma.sync.aligned.m16n8k16.row.col.f32.f16.f16.f32 "
        "{%0,%1,%2,%3},{%4,%5,%6,%7},{%8,%9},{%0,%1,%2,%3};"
        : "+f"(c[0]), "+f"(c[1]), "+f"(c[2]), "+f"(c[3])
        : "r"(a0), "r"(a1), "r"(a2), "r"(a3), "r"(b0), "r"(b1));
}

__device__ __forceinline__ void cp_async16(uint32_t dst, const void* src) {
    asm volatile("cp.async.cg.shared.global [%0], [%1], 16;"
                 :: "r"(dst), "l"(src) : "memory");
}

// ---------------- kernel P: kernel_u fp32 -> fp16 transposed [u][k] ----------------
__global__ void k_prep(const float* __restrict__ ku) {
    int i = blockIdx.x * blockDim.x + threadIdx.x;
    int stride = gridDim.x * blockDim.x;
    for (; i < 512 * 512; i += stride) {
        int u = i >> 9, k = i & 511;
        g_kuT[i] = __float2half(ku[k * 512 + u]);
    }
}

// ---------------- kernel A: s = h @ kernel_w + bias_u ----------------
__global__ void k_s(const float* __restrict__ h, const float* __restrict__ kw,
                    const float* __restrict__ bias) {
    __shared__ float hs[512];
    int b = blockIdx.x, u = threadIdx.x;
    hs[u] = h[b * 512 + u];
    __syncthreads();
    float acc = bias[2048 + u];
#pragma unroll 8
    for (int k = 0; k < 512; k++)
        acc += hs[k] * kw[k * 512 + u];
    g_s[b * 512 + u] = acc;
}

// ---------------- kernel B: attention scores (HMMA + cp.async pipeline) ----------------
// Per block: b = blockIdx.y, t0 = blockIdx.x*128.
// et[b,t] = sum_u tanh(ann[b,t,:]@ku[:,u] + s[b,u]) * kv[u]
// A tile 128x512 fp16 resident in smem; B ([64 u][128 k] chunks of g_kuT)
// double-buffered via cp.async; 32 chunks (8 u-chunks x 4 k-chunks).
static constexpr int SA = 520;                 // As row stride (halves)
static constexpr int SB = 136;                 // Bs row stride (halves)
static constexpr int AS_BYTES = 128 * SA * 2;  // 133120
static constexpr int BS_BYTES = 64 * SB * 2;   // 17408
static constexpr int B0_OFF = AS_BYTES;
static constexpr int SV_OFF = AS_BYTES + 2 * BS_BYTES;
static constexpr int SMEM_ATT = SV_OFF + 2 * 512 * 4;  // 172032

__global__ __launch_bounds__(256) void k_att(const float* __restrict__ ann,
                                             const float* __restrict__ kv) {
    extern __shared__ char sm[];
    __half* As = (__half*)sm;                               // [128][SA]
    float* s_s = (float*)(sm + SV_OFF);                     // [512]
    float* kv_s = s_s + 512;                                // [512]

    int b = blockIdx.y;
    int t0 = blockIdx.x * 128;
    int tid = threadIdx.x;
    uint32_t sb = smem_u32(sm);
    uint32_t bbuf[2] = { sb + B0_OFF, sb + B0_OFF + BS_BYTES };

    for (int i = tid; i < 512; i += 256) {
        s_s[i] = g_s[b * 512 + i];
        kv_s[i] = kv[i];
    }

    // Load A tile: ann[b, t0:t0+128, 0:512] fp32 -> fp16 smem
    const float* arow = ann + ((size_t)b * 2048 + t0) * 512;
    for (int i = tid; i < 128 * 128; i += 256) {   // float4 granules
        int r = i >> 7;
        int c4 = (i & 127) * 4;
        float4 v = *(const float4*)(arow + (size_t)r * 512 + c4);
        __half2 p0, p1;
        p0.x = __float2half(v.x); p0.y = __float2half(v.y);
        p1.x = __float2half(v.z); p1.y = __float2half(v.w);
        *(__half2*)(As + r * SA + c4) = p0;
        *(__half2*)(As + r * SA + c4 + 2) = p1;
    }

    int w = tid >> 5;
    int lane = tid & 31;
    int g = lane >> 2;    // row-in-stripe / n index
    int tg = lane & 3;    // thread-in-group

    float p1acc = 0.f, p2acc = 0.f;
    float acc[8][4];

    // Stage B chunk i into buffer: chunk i -> uc=i>>2, kc=i&3.
    // Bs[row][kk] = g_kuT[uc*64+row][kc*128+kk]; rows contiguous (256B = 16 granules).
    auto stage = [&](int i, uint32_t dst) {
        int uc = i >> 2, kc = i & 3;
        const __half* src = g_kuT + (size_t)(uc * 64) * 512 + kc * 128;
#pragma unroll
        for (int it = 0; it < 4; it++) {
            int idx = tid + it * 256;
            int row = idx >> 4, gi = idx & 15;
            cp_async16(dst + (uint32_t)(row * SB * 2 + gi * 16),
                       src + (size_t)row * 512 + gi * 8);
        }
        asm volatile("cp.async.commit_group;" ::: "memory");
    };

    stage(0, bbuf[0]);

    for (int i = 0; i < 32; i++) {
        int buf = i & 1, uc = i >> 2, kc = i & 3;

        __syncthreads();   // all warps done reading buf(i-1) before restaging it
        if (i + 1 < 32) {
            stage(i + 1, bbuf[buf ^ 1]);
            asm volatile("cp.async.wait_group 1;" ::: "memory");
        } else {
            asm volatile("cp.async.wait_group 0;" ::: "memory");
        }
        __syncthreads();   // chunk i visible to all warps (also guards As on i=0)

        if (kc == 0) {
#pragma unroll
            for (int n0 = 0; n0 < 8; n0++)
#pragma unroll
                for (int q = 0; q < 4; q++) acc[n0][q] = 0.f;
        }

        const __half* Bs = (__half*)(sm + B0_OFF + buf * BS_BYTES);
#pragma unroll
        for (int ks = 0; ks < 8; ks++) {
            int k0 = ks * 16;
            const __half* ab = As + (w * 16 + g) * SA + kc * 128 + k0 + tg * 2;
            uint32_t a0 = *(const uint32_t*)ab;
            uint32_t a1 = *(const uint32_t*)(ab + 8 * SA);
            uint32_t a2 = *(const uint32_t*)(ab + 8);
            uint32_t a3 = *(const uint32_t*)(ab + 8 * SA + 8);
#pragma unroll
            for (int n0 = 0; n0 < 8; n0++) {
                const __half* bb = Bs + (n0 * 8 + g) * SB + k0 + tg * 2;
                uint32_t b0 = *(const uint32_t*)bb;
                uint32_t b1 = *(const uint32_t*)(bb + 8);
                mma16816(acc[n0], a0, a1, a2, a3, b0, b1);
            }
        }

        if (kc == 3) {
            // Epilogue for this u-chunk: tanh(uh + s) * kv -> row partials
#pragma unroll
            for (int n0 = 0; n0 < 8; n0++) {
                int ub = uc * 64 + n0 * 8 + tg * 2;
                float s0 = s_s[ub], s1 = s_s[ub + 1];
                float v0 = kv_s[ub], v1 = kv_s[ub + 1];
                p1acc += tanhp(acc[n0][0] + s0) * v0 + tanhp(acc[n0][1] + s1) * v1;
                p2acc += tanhp(acc[n0][2] + s0) * v0 + tanhp(acc[n0][3] + s1) * v1;
            }
        }
    }

    // Reduce across the 4 lanes sharing a row
    p1acc += __shfl_xor_sync(0xffffffffu, p1acc, 1);
    p1acc += __shfl_xor_sync(0xffffffffu, p1acc, 2);
    p2acc += __shfl_xor_sync(0xffffffffu, p2acc, 1);
    p2acc += __shfl_xor_sync(0xffffffffu, p2acc, 2);
    if (tg == 0) {
        g_et[b * 2048 + t0 + w * 16 + g] = p1acc;
        g_et[b * 2048 + t0 + w * 16 + g + 8] = p2acc;
    }
}

// ---------------- kernel C: softmax over t (in place), zero ctx ----------------
__global__ void k_softmax() {
    __shared__ float red[512];
    int b = blockIdx.x, tid = threadIdx.x;
    float v[4];
    float mx = -1e30f;
#pragma unroll
    for (int j = 0; j < 4; j++) {
        v[j] = g_et[b * 2048 + j * 512 + tid];
        mx = fmaxf(mx, v[j]);
    }
    red[tid] = mx;
    __syncthreads();
    for (int s = 256; s > 0; s >>= 1) {
        if (tid < s) red[tid] = fmaxf(red[tid], red[tid + s]);
        __syncthreads();
    }
    mx = red[0];
    __syncthreads();
    float sum = 0.f;
#pragma unroll
    for (int j = 0; j < 4; j++) {
        v[j] = expf(v[j] - mx);
        sum += v[j];
    }
    red[tid] = sum;
    __syncthreads();
    for (int s = 256; s > 0; s >>= 1) {
        if (tid < s) red[tid] += red[tid + s];
        __syncthreads();
    }
    float inv = 1.f / red[0];
#pragma unroll
    for (int j = 0; j < 4; j++)
        g_et[b * 2048 + j * 512 + tid] = v[j] * inv;
    g_ctx[b * 512 + tid] = 0.f;
}

// ---------------- kernel D: context = at . annotations ----------------
__global__ __launch_bounds__(256) void k_ctx(const float* __restrict__ ann) {
    __shared__ float at_s[512];
    int ac = blockIdx.x, tc = blockIdx.y, b = blockIdx.z;
    int tid = threadIdx.x;
    int tbase = tc * 512, a0 = ac * 256;
    at_s[tid] = g_et[b * 2048 + tbase + tid];
    at_s[tid + 256] = g_et[b * 2048 + tbase + tid + 256];
    __syncthreads();
    const float* base = ann + ((size_t)b * 2048 + tbase) * 512 + a0 + tid;
    float acc = 0.f;
#pragma unroll 4
    for (int t = 0; t < 512; t++)
        acc += at_s[t] * base[(size_t)t * 512];
    atomicAdd(&g_ctx[b * 512 + a0 + tid], acc);
}

// ---------------- kernel E1: z = [inputs,ctx,h] @ [kernel;rk] + bias ----------------
__global__ __launch_bounds__(256) void k_z(const float* __restrict__ inputs,
                                           const float* __restrict__ h,
                                           const float* __restrict__ kern,
                                           const float* __restrict__ rk,
                                           const float* __restrict__ bias) {
    __shared__ float xs[64][33];
    __shared__ float ws[32][33];
    int j0 = blockIdx.x * 32;
    int tid = threadIdx.x;
    int tj = tid & 15, tb = tid >> 4;
    float acc[4][2] = {};
    for (int kc = 0; kc < 48; kc++) {
        int k0 = kc * 32;
        for (int i = tid; i < 2048; i += 256) {
            int bb = i >> 5, k = i & 31;
            int kk = k0 + k;
            float v;
            if (kk < 512)        v = inputs[bb * 512 + kk];
            else if (kk < 1024)  v = g_ctx[bb * 512 + kk - 512];
            else                 v = h[bb * 512 + kk - 1024];
            xs[bb][k] = v;
        }
        for (int i = tid; i < 1024; i += 256) {
            int k = i >> 5, j = i & 31;
            int kk = k0 + k;
            float v = (kk < 1024) ? kern[(size_t)kk * 2048 + j0 + j]
                                  : rk[(size_t)(kk - 1024) * 2048 + j0 + j];
            ws[k][j] = v;
        }
        __syncthreads();
#pragma unroll 8
        for (int k = 0; k < 32; k++) {
            float w0 = ws[k][tj * 2], w1 = ws[k][tj * 2 + 1];
#pragma unroll
            for (int bb = 0; bb < 4; bb++) {
                float x = xs[tb * 4 + bb][k];
                acc[bb][0] += x * w0;
                acc[bb][1] += x * w1;
            }
        }
        __syncthreads();
    }
#pragma unroll
    for (int bb = 0; bb < 4; bb++) {
        int bi = tb * 4 + bb;
        int j = j0 + tj * 2;
        g_z[bi * 2048 + j]     = acc[bb][0] + bias[j];
        g_z[bi * 2048 + j + 1] = acc[bb][1] + bias[j + 1];
    }
}

// ---------------- kernel E2: gates + h_new ----------------
__global__ void k_gate(const float* __restrict__ c, float* __restrict__ out) {
    int b = blockIdx.x, u = threadIdx.x;
    float zi = g_z[b * 2048 + u];
    float zf = g_z[b * 2048 + 512 + u];
    float zg = g_z[b * 2048 + 1024 + u];
    float zo = g_z[b * 2048 + 1536 + u];
    float ig = fminf(fmaxf(0.2f * zi + 0.5f, 0.f), 1.f);
    float fg = fminf(fmaxf(0.2f * zf + 0.5f, 0.f), 1.f);
    float og = fminf(fmaxf(0.2f * zo + 0.5f, 0.f), 1.f);
    float cn = fg * c[b * 512 + u] + ig * tanhf(zg);
    out[b * 512 + u] = og * tanhf(cn);
}

// ---------------- launch ----------------
extern "C" void kernel_launch(void* const* d_in, const int* in_sizes, int n_in,
                              void* d_out, int out_size) {
    const float* inputs = (const float*)d_in[0];
    const float* h      = (const float*)d_in[1];
    const float* c      = (const float*)d_in[2];
    const float* ann    = (const float*)d_in[3];
    const float* kern   = (const float*)d_in[4];
    const float* rk     = (const float*)d_in[5];
    const float* bias   = (const float*)d_in[6];
    const float* ku     = (const float*)d_in[7];
    const float* kw     = (const float*)d_in[8];
    const float* kv     = (const float*)d_in[9];
    float* out = (float*)d_out;

    cudaFuncSetAttribute(k_att, cudaFuncAttributeMaxDynamicSharedMemorySize, SMEM_ATT);

    k_prep<<<512, 256>>>(ku);
    k_s<<<64, 512>>>(h, kw, bias);
    dim3 gb(16, 64);
    k_att<<<gb, 256, SMEM_ATT>>>(ann, kv);
    k_softmax<<<64, 512>>>();
    dim3 gd(2, 4, 64);
    k_ctx<<<gd, 256>>>(ann);
    k_z<<<64, 256>>>(inputs, h, kern, rk, bias);
    k_gate<<<64, 512>>>(c, out);
}